// round 11
// baseline (speedup 1.0000x reference)
#include <cuda_runtime.h>
#include <cuda_bf16.h>
#include <cstdint>
#include <cstring>

#define BATCH 4096
#define DIM   256
#define NREL  30
#define GS    32          // samples per group (MMA M dim)
#define MAXG  160         // >= 30 + 4096/32
#define NTH   256
#define KC    32          // K rows per chunk
#define KSPLIT 2          // K halves (CTAs per group)
#define LCHUNKS 4         // chunks per CTA
#define AST   40          // A bf16 tile row stride (halves)
#define BST   264         // B bf16 tile row stride (halves)
#define TST   260         // tT row stride (floats)

// SMEM byte offsets
#define OFF_SIDX  0                      // 32 ints (128B)
#define OFF_RED   128                    // 128 floats (512B)
#define OFF_ATILE 640                    // [2 mat][32][40] halves = 5120B
#define OFF_BTILE 5760                   // [2 mat][32][264] halves = 33792B
#define OFF_STAGE 39552                  // [32][256] fp32 = 32768B (single buffer)
#define SMEM_BYTES 72320                 // x3 CTAs = 216960 <= 228KB/SM
// epilogue: tT[32][260] fp32 = 33280B reuses OFF_ATILE.. (38912B of dead tiles)

// ---- device scratch ----
__device__ int g_grp_rel[MAXG];
__device__ int g_grp_start[MAXG];
__device__ int g_sorted[MAXG * GS];
__device__ int g_ngrp;

// ---- helpers ----
__device__ __forceinline__ uint32_t smem_u32(const void* p) {
    uint32_t a;
    asm("{ .reg .u64 t; cvta.to.shared.u64 t, %1; cvt.u32.u64 %0, t; }" : "=r"(a) : "l"(p));
    return a;
}
__device__ __forceinline__ void cpasync16(uint32_t dst, const void* src) {
    asm volatile("cp.async.cg.shared.global [%0], [%1], 16;" :: "r"(dst), "l"(src));
}
__device__ __forceinline__ void ldm_x4(uint32_t* r, uint32_t addr) {
    asm volatile("ldmatrix.sync.aligned.m8n8.x4.shared.b16 {%0,%1,%2,%3}, [%4];"
                 : "=r"(r[0]), "=r"(r[1]), "=r"(r[2]), "=r"(r[3]) : "r"(addr));
}
__device__ __forceinline__ void ldm_x4_t(uint32_t* r, uint32_t addr) {
    asm volatile("ldmatrix.sync.aligned.m8n8.x4.trans.shared.b16 {%0,%1,%2,%3}, [%4];"
                 : "=r"(r[0]), "=r"(r[1]), "=r"(r[2]), "=r"(r[3]) : "r"(addr));
}
__device__ __forceinline__ void mma_bf16(float* c, const uint32_t* a, const uint32_t* b) {
    asm volatile("mma.sync.aligned.m16n8k16.row.col.f32.bf16.bf16.f32 "
                 "{%0,%1,%2,%3}, {%4,%5,%6,%7}, {%8,%9}, {%0,%1,%2,%3};"
                 : "+f"(c[0]), "+f"(c[1]), "+f"(c[2]), "+f"(c[3])
                 : "r"(a[0]), "r"(a[1]), "r"(a[2]), "r"(a[3]), "r"(b[0]), "r"(b[1]));
}
__device__ __forceinline__ void sts8(uint32_t addr, uint32_t lo, uint32_t hi) {
    asm volatile("st.shared.v2.b32 [%0], {%1,%2};" :: "r"(addr), "r"(lo), "r"(hi) : "memory");
}
__device__ __forceinline__ uint32_t bf2bits(__nv_bfloat162 v) {
    uint32_t u; memcpy(&u, &v, 4); return u;
}
// split float4 into big/small bf16x2 pairs (bit patterns)
__device__ __forceinline__ void split4(float4 v, uint32_t& b0, uint32_t& b1,
                                       uint32_t& s0, uint32_t& s1) {
    __nv_bfloat162 bb0 = __float22bfloat162_rn(make_float2(v.x, v.y));
    __nv_bfloat162 bb1 = __float22bfloat162_rn(make_float2(v.z, v.w));
    float2 f0 = __bfloat1622float2(bb0), f1 = __bfloat1622float2(bb1);
    __nv_bfloat162 ss0 = __float22bfloat162_rn(make_float2(v.x - f0.x, v.y - f0.y));
    __nv_bfloat162 ss1 = __float22bfloat162_rn(make_float2(v.z - f1.x, v.w - f1.y));
    b0 = bf2bits(bb0); b1 = bf2bits(bb1); s0 = bf2bits(ss0); s1 = bf2bits(ss1);
}

// ---------------------------------------------------------------------------
// Kernel 1: grouping (1 CTA, 1024 thr) + zero out. ids int32/int64-robust.
// ---------------------------------------------------------------------------
__global__ void group_kernel(const int* __restrict__ ids32, float* __restrict__ out) {
    __shared__ int cnt[NREL];
    __shared__ int fill[NREL];
    __shared__ int pad_off[NREL + 1];
    __shared__ int odd_nonzero;
    int tid = threadIdx.x;

    for (int i = tid; i < BATCH; i += 1024) out[i] = 0.0f;

    if (tid < NREL) { cnt[tid] = 0; fill[tid] = 0; }
    if (tid == 0) odd_nonzero = 0;
    __syncthreads();
    for (int i = tid; i < BATCH / 2; i += 1024)
        if (ids32[2 * i + 1] != 0) odd_nonzero = 1;
    __syncthreads();
    const int stride = odd_nonzero ? 1 : 2;   // int32 : int64 low word

    for (int i = tid; i < BATCH; i += 1024) {
        int r = ids32[i * stride];
        if ((unsigned)r < NREL) atomicAdd(&cnt[r], 1);
    }
    __syncthreads();

    if (tid == 0) {
        int off = 0, t = 0;
        for (int r = 0; r < NREL; r++) {
            pad_off[r] = off;
            int ng = (cnt[r] + GS - 1) / GS;
            for (int k = 0; k < ng; k++) {
                g_grp_rel[t] = r;
                g_grp_start[t] = off + k * GS;
                t++;
            }
            off += ng * GS;
        }
        g_ngrp = t;
    }
    __syncthreads();

    for (int i = tid; i < MAXG * GS; i += 1024) g_sorted[i] = -1;
    __syncthreads();

    for (int i = tid; i < BATCH; i += 1024) {
        int r = ids32[i * stride];
        if ((unsigned)r < NREL) {
            int p = pad_off[r] + atomicAdd(&fill[r], 1);
            g_sorted[p] = i;
        }
    }
}

// ---------------------------------------------------------------------------
// Kernel 2: CTA = (group, k-half). In-kernel fp32->big/small bf16 conversion,
// single 32KB staging buffer, 3 CTAs/SM. 3-pass mma.sync; deterministic
// epilogue (2 commutative atomicAdds per sample).
// ---------------------------------------------------------------------------
extern __shared__ char smem[];

__global__ __launch_bounds__(NTH, 3)
void mma_kernel(const float* __restrict__ head,
                const float* __restrict__ tail,
                const float* __restrict__ relmat,
                float* __restrict__ out) {
    int g  = blockIdx.x >> 1;
    int kh = blockIdx.x & 1;
    if (g >= g_ngrp) return;

    int tid = threadIdx.x, wid = tid >> 5, l = tid & 31;
    int mw = wid & 1;          // m-tile (16 rows)
    int nw = wid >> 1;         // n-warp (64 cols)
    uint32_t sb = smem_u32(smem);
    int* s_idx = (int*)(smem + OFF_SIDX);
    float* red = (float*)(smem + OFF_RED);

    int r = g_grp_rel[g];
    int start = g_grp_start[g];
    if (tid < GS) s_idx[tid] = g_sorted[start + tid];
    __syncthreads();

    const float* Mf = relmat + (size_t)r * DIM * DIM + (size_t)kh * (DIM / 2) * DIM;
    const int kbase = kh * (DIM / 2);    // this CTA's K offset into H

    // B fp32 staging issue (single buffer)
    auto issueB = [&](int kc) {
        const float* src = Mf + (size_t)kc * KC * DIM;
        #pragma unroll
        for (int k = 0; k < 8; k++) {
            int e = tid + k * NTH;                       // < 2048 float4
            cpasync16(sb + OFF_STAGE + e * 16, src + e * 4);
        }
        asm volatile("cp.async.commit_group;" ::: "memory");
    };
    issueB(0);

    float c[8][4];
    #pragma unroll
    for (int nf = 0; nf < 8; nf++)
        #pragma unroll
        for (int k = 0; k < 4; k++) c[nf][k] = 0.f;

    uint32_t a_row  = mw * 16 + (l & 15);
    uint32_t a_koff = (uint32_t)((l >> 4) << 3);
    uint32_t b_krow = (uint32_t)(l & 15);
    uint32_t b_ncol = (uint32_t)(nw * 64 + ((l >> 4) << 3));

    const int As = tid >> 3, Au = tid & 7;   // A load mapping: sample, float4-col
    const int gia = s_idx[As];

    for (int kc = 0; kc < LCHUNKS; kc++) {
        // A fp32 for this chunk (1 float4/thread)
        float4 av = make_float4(0.f, 0.f, 0.f, 0.f);
        if (gia >= 0)
            av = *(const float4*)(head + (size_t)gia * DIM + kbase + kc * KC + Au * 4);

        asm volatile("cp.async.wait_group 0;" ::: "memory");
        __syncthreads();   // stage has chunk kc; tiles free (compute kc-1 done)

        // ---- convert B: staging fp32 -> big/small bf16 tiles ----
        const float4* st4 = (const float4*)(smem + OFF_STAGE);
        #pragma unroll
        for (int k = 0; k < 8; k++) {
            int e = tid + k * NTH;
            int kr = e >> 6, c4 = e & 63;
            uint32_t b0, b1, s0, s1;
            split4(st4[e], b0, b1, s0, s1);
            uint32_t addr = sb + OFF_BTILE + (uint32_t)(kr * (BST * 2) + c4 * 8);
            sts8(addr, b0, b1);
            sts8(addr + 16896, s0, s1);
        }
        // ---- convert A ----
        {
            uint32_t b0, b1, s0, s1;
            split4(av, b0, b1, s0, s1);
            uint32_t addr = sb + OFF_ATILE + (uint32_t)(As * (AST * 2) + Au * 8);
            sts8(addr, b0, b1);
            sts8(addr + 2560, s0, s1);
        }
        __syncthreads();   // tiles ready; stage free
        if (kc + 1 < LCHUNKS) issueB(kc + 1);   // overlaps compute below

        // ---- compute ----
        uint32_t Ab0 = sb + OFF_ATILE;
        uint32_t Ab1 = sb + OFF_ATILE + 2560;
        uint32_t Bb0 = sb + OFF_BTILE;
        uint32_t Bb1 = sb + OFF_BTILE + 16896;

        #pragma unroll
        for (int ks = 0; ks < KC / 16; ks++) {
            uint32_t aB[4], aS[4];
            uint32_t ka = ks * 16 + a_koff;
            ldm_x4(aB, Ab0 + (a_row * AST + ka) * 2);
            ldm_x4(aS, Ab1 + (a_row * AST + ka) * 2);
            #pragma unroll
            for (int nt = 0; nt < 4; nt++) {
                uint32_t bB[4], bS[4];
                uint32_t boff = ((ks * 16 + b_krow) * BST + b_ncol + nt * 16) * 2;
                ldm_x4_t(bB, Bb0 + boff);
                ldm_x4_t(bS, Bb1 + boff);
                mma_bf16(c[2 * nt],     aB, bB);
                mma_bf16(c[2 * nt + 1], aB, bB + 2);
                mma_bf16(c[2 * nt],     aB, bS);
                mma_bf16(c[2 * nt + 1], aB, bS + 2);
                mma_bf16(c[2 * nt],     aS, bB);
                mma_bf16(c[2 * nt + 1], aS, bB + 2);
            }
        }
    }

    // ---- epilogue: load t into tT (reusing dead tile SMEM), fold, reduce ----
    __syncthreads();   // all warps done reading tiles
    float* tT = (float*)(smem + OFF_ATILE);
    #pragma unroll
    for (int k = 0; k < 8; k++) {
        int e = tid + k * NTH;
        int s = e >> 6, cc = e & 63;
        int gi = s_idx[s];
        float4 tv = make_float4(0.f, 0.f, 0.f, 0.f);
        if (gi >= 0) tv = ((const float4*)(tail + (size_t)gi * DIM))[cc];
        *(float4*)(tT + s * TST + cc * 4) = tv;
    }
    __syncthreads();

    int q = l & 3, a = l >> 2;
    int row0 = mw * 16 + a, row1 = row0 + 8;
    float p0 = 0.f, p1 = 0.f;
    #pragma unroll
    for (int nf = 0; nf < 8; nf++) {
        int j = nw * 64 + nf * 8 + q * 2;
        p0 += c[nf][0] * tT[row0 * TST + j] + c[nf][1] * tT[row0 * TST + j + 1];
        p1 += c[nf][2] * tT[row1 * TST + j] + c[nf][3] * tT[row1 * TST + j + 1];
    }
    p0 += __shfl_xor_sync(0xFFFFFFFF, p0, 1);
    p0 += __shfl_xor_sync(0xFFFFFFFF, p0, 2);
    p1 += __shfl_xor_sync(0xFFFFFFFF, p1, 1);
    p1 += __shfl_xor_sync(0xFFFFFFFF, p1, 2);
    if (q == 0) {
        red[nw * 32 + row0] = p0;
        red[nw * 32 + row1] = p1;
    }
    __syncthreads();

    if (tid < GS) {
        int gi = s_idx[tid];
        if (gi >= 0)
            atomicAdd(&out[gi], red[tid] + red[32 + tid] + red[64 + tid] + red[96 + tid]);
    }
}

// ---------------------------------------------------------------------------
// Launch: resolve input slots by element count.
// ---------------------------------------------------------------------------
extern "C" void kernel_launch(void* const* d_in, const int* in_sizes, int n_in,
                              void* d_out, int out_size) {
    const float* head = nullptr;
    const float* tail = nullptr;
    const int*   ids  = nullptr;
    const float* relmat = nullptr;

    for (int i = 0; i < n_in; i++) {
        if (in_sizes[i] == BATCH)                 ids    = (const int*)d_in[i];
        else if (in_sizes[i] == NREL * DIM * DIM) relmat = (const float*)d_in[i];
        else if (in_sizes[i] == BATCH * DIM) {
            if (!head) head = (const float*)d_in[i];
            else       tail = (const float*)d_in[i];
        }
    }
    float* out = (float*)d_out;

    cudaFuncSetAttribute(mma_kernel,
                         cudaFuncAttributeMaxDynamicSharedMemorySize, SMEM_BYTES);

    group_kernel<<<1, 1024>>>(ids, out);
    mma_kernel<<<MAXG * KSPLIT, NTH, SMEM_BYTES>>>(head, tail, relmat, out);
}

// round 12
// speedup vs baseline: 1.2102x; 1.2102x over previous
#include <cuda_runtime.h>
#include <cuda_bf16.h>
#include <cstdint>
#include <cstring>

#define BATCH 4096
#define DIM   256
#define NREL  30
#define GS    32          // samples per group (MMA M dim)
#define MAXG  160         // >= 30 + 4096/32
#define NTH   256
#define KC    32          // K rows per chunk
#define KSPLIT 2          // K halves (CTAs per group)
#define LCHUNKS 4         // chunks per CTA
#define AST   40          // A bf16 tile row stride (halves)
#define BST   264         // B bf16 tile row stride (halves)
#define TST   260         // tT row stride (floats)
#define IDSPT (BATCH / NTH)   // 16 ids per thread

// SMEM byte offsets
#define OFF_SIDX  0                      // 32 ints (128B)
#define OFF_RED   128                    // 512B: epilogue red[128]f; phase0 cnt[32]+wtot[8]
#define OFF_MISC  640                    // 128B flags: [0]=r, [1]=k, [2]=odd, [3]=lastf
#define OFF_ATILE 768                    // [2 mat][32][40] halves = 5120B
#define OFF_BTILE 5888                   // [2 mat][32][264] halves = 33792B
#define OFF_STAGE 39680                  // [2 buf][32][256] fp32 = 65536B (tT reuse at epilogue)
#define SMEM_BYTES 105216                // x2 CTAs = 210432 <= 227KB/SM

// ---- device scratch (zero-initialized at module load; kernel restores zeros) ----
__device__ float g_partial[BATCH];
__device__ int   g_cnt[MAXG];

// ---- helpers ----
__device__ __forceinline__ uint32_t smem_u32(const void* p) {
    uint32_t a;
    asm("{ .reg .u64 t; cvta.to.shared.u64 t, %1; cvt.u32.u64 %0, t; }" : "=r"(a) : "l"(p));
    return a;
}
__device__ __forceinline__ void cpasync16(uint32_t dst, const void* src) {
    asm volatile("cp.async.cg.shared.global [%0], [%1], 16;" :: "r"(dst), "l"(src));
}
__device__ __forceinline__ void ldm_x4(uint32_t* r, uint32_t addr) {
    asm volatile("ldmatrix.sync.aligned.m8n8.x4.shared.b16 {%0,%1,%2,%3}, [%4];"
                 : "=r"(r[0]), "=r"(r[1]), "=r"(r[2]), "=r"(r[3]) : "r"(addr));
}
__device__ __forceinline__ void ldm_x4_t(uint32_t* r, uint32_t addr) {
    asm volatile("ldmatrix.sync.aligned.m8n8.x4.trans.shared.b16 {%0,%1,%2,%3}, [%4];"
                 : "=r"(r[0]), "=r"(r[1]), "=r"(r[2]), "=r"(r[3]) : "r"(addr));
}
__device__ __forceinline__ void mma_bf16(float* c, const uint32_t* a, const uint32_t* b) {
    asm volatile("mma.sync.aligned.m16n8k16.row.col.f32.bf16.bf16.f32 "
                 "{%0,%1,%2,%3}, {%4,%5,%6,%7}, {%8,%9}, {%0,%1,%2,%3};"
                 : "+f"(c[0]), "+f"(c[1]), "+f"(c[2]), "+f"(c[3])
                 : "r"(a[0]), "r"(a[1]), "r"(a[2]), "r"(a[3]), "r"(b[0]), "r"(b[1]));
}
__device__ __forceinline__ void sts8(uint32_t addr, uint32_t lo, uint32_t hi) {
    asm volatile("st.shared.v2.b32 [%0], {%1,%2};" :: "r"(addr), "r"(lo), "r"(hi) : "memory");
}
__device__ __forceinline__ uint32_t bf2bits(__nv_bfloat162 v) {
    uint32_t u; memcpy(&u, &v, 4); return u;
}
__device__ __forceinline__ void split4(float4 v, uint32_t& b0, uint32_t& b1,
                                       uint32_t& s0, uint32_t& s1) {
    __nv_bfloat162 bb0 = __float22bfloat162_rn(make_float2(v.x, v.y));
    __nv_bfloat162 bb1 = __float22bfloat162_rn(make_float2(v.z, v.w));
    float2 f0 = __bfloat1622float2(bb0), f1 = __bfloat1622float2(bb1);
    __nv_bfloat162 ss0 = __float22bfloat162_rn(make_float2(v.x - f0.x, v.y - f0.y));
    __nv_bfloat162 ss1 = __float22bfloat162_rn(make_float2(v.z - f1.x, v.w - f1.y));
    b0 = bf2bits(bb0); b1 = bf2bits(bb1); s0 = bf2bits(ss0); s1 = bf2bits(ss1);
}

// ---------------------------------------------------------------------------
// SINGLE kernel: CTA = (group g = blockIdx>>1, k-half). Phase 0 derives the
// group table + this CTA's 32 sample indices from ids (redundantly per CTA,
// deterministic index-order). Then R10's proven double-buffered 3-pass bf16
// mma.sync mainloop. Paired-CTA combine via g_partial + arrival counter
// (self-resetting -> graph-replay safe).
// ---------------------------------------------------------------------------
extern __shared__ char smem[];

__global__ __launch_bounds__(NTH, 2)
void mma_kernel(const float* __restrict__ head,
                const float* __restrict__ tail,
                const float* __restrict__ relmat,
                const int* __restrict__ ids32,
                float* __restrict__ out) {
    const int g  = blockIdx.x >> 1;
    const int kh = blockIdx.x & 1;
    const int tid = threadIdx.x, wid = tid >> 5, l = tid & 31;
    uint32_t sb = smem_u32(smem);
    int* s_idx = (int*)(smem + OFF_SIDX);
    float* red = (float*)(smem + OFF_RED);
    int* scr   = (int*)(smem + OFF_RED);    // phase0: cnt[32], wtot at +32
    int* misc  = (int*)(smem + OFF_MISC);

    // ================= Phase 0: derive grouping (per-CTA, deterministic) ====
    if (tid < 32) scr[tid] = 0;             // cnt
    if (tid < GS) s_idx[tid] = -1;
    if (tid == 0) misc[2] = 0;              // odd flag
    __syncthreads();

    // int64-vs-int32 detection: any nonzero odd word => int32 data
    {
        int any = 0;
        #pragma unroll
        for (int j = 0; j < 8; j++)
            any |= ids32[2 * (tid * 8 + j) + 1];
        if (__syncthreads_or(any)) { if (tid == 0) misc[2] = 1; }
        __syncthreads();
    }
    const int stride = misc[2] ? 1 : 2;

    // load my 16 consecutive ids; histogram
    int my_ids[IDSPT];
    #pragma unroll
    for (int j = 0; j < IDSPT; j++) {
        int v = ids32[(tid * IDSPT + j) * stride];
        my_ids[j] = ((unsigned)v < NREL) ? v : 0;
        atomicAdd(&scr[my_ids[j]], 1);
    }
    __syncthreads();

    // thread 0: map g -> (relation, k-slice)
    if (tid == 0) {
        int base = 0, rmy = -1, kmy = 0;
        #pragma unroll
        for (int rr = 0; rr < NREL; rr++) {
            int ngr = (scr[rr] + GS - 1) / GS;
            if (g >= base && g < base + ngr) { rmy = rr; kmy = g - base; }
            base += ngr;
        }
        misc[0] = rmy; misc[1] = kmy;
    }
    __syncthreads();
    const int r = misc[0], kslice = misc[1];
    if (r < 0) return;                      // dummy group

    // stable rank scan for relation r (thread-order = index-order)
    {
        int cntm = 0;
        #pragma unroll
        for (int j = 0; j < IDSPT; j++) cntm += (my_ids[j] == r);
        int pre = cntm;
        #pragma unroll
        for (int d = 1; d < 32; d <<= 1) {
            int v = __shfl_up_sync(0xFFFFFFFF, pre, d);
            if (l >= d) pre += v;
        }
        __syncthreads();                    // scr histogram reads done
        if (l == 31) scr[wid] = pre;        // warp totals (reuse scr[0..7])
        int excl = pre - cntm;
        __syncthreads();
        int base = 0;
        for (int ww = 0; ww < wid; ww++) base += scr[ww];
        int rank = base + excl;
        int lo = kslice * GS, hi = lo + GS;
        #pragma unroll
        for (int j = 0; j < IDSPT; j++) {
            if (my_ids[j] == r) {
                if (rank >= lo && rank < hi) s_idx[rank - lo] = tid * IDSPT + j;
                rank++;
            }
        }
    }
    __syncthreads();

    // ================= Mainloop (R10 verbatim, offsets shifted) =============
    const int mw = wid & 1;          // m-tile (16 rows)
    const int nw = wid >> 1;         // n-warp (64 cols)
    const float* Mf = relmat + (size_t)r * DIM * DIM + (size_t)kh * (DIM / 2) * DIM;
    const int kbase = kh * (DIM / 2);

    // Preload t into registers
    float4 treg[8];
    #pragma unroll
    for (int k = 0; k < 8; k++) {
        int e = tid + k * NTH;
        int s = e >> 6, cc = e & 63;
        int gi = s_idx[s];
        treg[k] = make_float4(0.f, 0.f, 0.f, 0.f);
        if (gi >= 0) treg[k] = ((const float4*)(tail + (size_t)gi * DIM))[cc];
    }

    auto issueB = [&](int kc, int buf) {
        const float* src = Mf + (size_t)kc * KC * DIM;
        #pragma unroll
        for (int k = 0; k < 8; k++) {
            int e = tid + k * NTH;
            cpasync16(sb + OFF_STAGE + buf * 32768 + e * 16, src + e * 4);
        }
        asm volatile("cp.async.commit_group;" ::: "memory");
    };
    issueB(0, 0);
    issueB(1, 1);

    float c[8][4];
    #pragma unroll
    for (int nf = 0; nf < 8; nf++)
        #pragma unroll
        for (int k = 0; k < 4; k++) c[nf][k] = 0.f;

    uint32_t a_row  = mw * 16 + (l & 15);
    uint32_t a_koff = (uint32_t)((l >> 4) << 3);
    uint32_t b_krow = (uint32_t)(l & 15);
    uint32_t b_ncol = (uint32_t)(nw * 64 + ((l >> 4) << 3));

    const int As = tid >> 3, Au = tid & 7;
    const int gia = s_idx[As];

    for (int kc = 0; kc < LCHUNKS; kc++) {
        float4 av = make_float4(0.f, 0.f, 0.f, 0.f);
        if (gia >= 0)
            av = *(const float4*)(head + (size_t)gia * DIM + kbase + kc * KC + Au * 4);

        if (kc == LCHUNKS - 1)
            asm volatile("cp.async.wait_group 0;" ::: "memory");
        else
            asm volatile("cp.async.wait_group 1;" ::: "memory");
        __syncthreads();

        const float4* st4 = (const float4*)(smem + OFF_STAGE + (kc & 1) * 32768);
        #pragma unroll
        for (int k = 0; k < 8; k++) {
            int e = tid + k * NTH;
            int kr = e >> 6, c4 = e & 63;
            uint32_t b0, b1, s0, s1;
            split4(st4[e], b0, b1, s0, s1);
            uint32_t addr = sb + OFF_BTILE + (uint32_t)(kr * (BST * 2) + c4 * 8);
            sts8(addr, b0, b1);
            sts8(addr + 16896, s0, s1);
        }
        {
            uint32_t b0, b1, s0, s1;
            split4(av, b0, b1, s0, s1);
            uint32_t addr = sb + OFF_ATILE + (uint32_t)(As * (AST * 2) + Au * 8);
            sts8(addr, b0, b1);
            sts8(addr + 2560, s0, s1);
        }
        __syncthreads();
        if (kc + 2 < LCHUNKS) issueB(kc + 2, kc & 1);

        uint32_t Ab0 = sb + OFF_ATILE;
        uint32_t Ab1 = sb + OFF_ATILE + 2560;
        uint32_t Bb0 = sb + OFF_BTILE;
        uint32_t Bb1 = sb + OFF_BTILE + 16896;

        #pragma unroll
        for (int ks = 0; ks < KC / 16; ks++) {
            uint32_t aB[4], aS[4];
            uint32_t ka = ks * 16 + a_koff;
            ldm_x4(aB, Ab0 + (a_row * AST + ka) * 2);
            ldm_x4(aS, Ab1 + (a_row * AST + ka) * 2);
            #pragma unroll
            for (int nt = 0; nt < 4; nt++) {
                uint32_t bB[4], bS[4];
                uint32_t boff = ((ks * 16 + b_krow) * BST + b_ncol + nt * 16) * 2;
                ldm_x4_t(bB, Bb0 + boff);
                ldm_x4_t(bS, Bb1 + boff);
                mma_bf16(c[2 * nt],     aB, bB);
                mma_bf16(c[2 * nt + 1], aB, bB + 2);
                mma_bf16(c[2 * nt],     aB, bS);
                mma_bf16(c[2 * nt + 1], aB, bS + 2);
                mma_bf16(c[2 * nt],     aS, bB);
                mma_bf16(c[2 * nt + 1], aS, bB + 2);
            }
        }
    }

    // ================= Epilogue: fold t, reduce, paired combine =============
    float* tT = (float*)(smem + OFF_STAGE);
    #pragma unroll
    for (int k = 0; k < 8; k++) {
        int e = tid + k * NTH;
        int s = e >> 6, cc = e & 63;
        *(float4*)(tT + s * TST + cc * 4) = treg[k];
    }
    __syncthreads();

    int q = l & 3, a = l >> 2;
    int row0 = mw * 16 + a, row1 = row0 + 8;
    float p0 = 0.f, p1 = 0.f;
    #pragma unroll
    for (int nf = 0; nf < 8; nf++) {
        int j = nw * 64 + nf * 8 + q * 2;
        p0 += c[nf][0] * tT[row0 * TST + j] + c[nf][1] * tT[row0 * TST + j + 1];
        p1 += c[nf][2] * tT[row1 * TST + j] + c[nf][3] * tT[row1 * TST + j + 1];
    }
    p0 += __shfl_xor_sync(0xFFFFFFFF, p0, 1);
    p0 += __shfl_xor_sync(0xFFFFFFFF, p0, 2);
    p1 += __shfl_xor_sync(0xFFFFFFFF, p1, 1);
    p1 += __shfl_xor_sync(0xFFFFFFFF, p1, 2);
    if (q == 0) {
        red[nw * 32 + row0] = p0;
        red[nw * 32 + row1] = p1;
    }
    __syncthreads();

    // release: add partial, fence, then count arrival
    if (tid < GS) {
        int gi = s_idx[tid];
        if (gi >= 0)
            atomicAdd(&g_partial[gi],
                      red[tid] + red[32 + tid] + red[64 + tid] + red[96 + tid]);
        __threadfence();
    }
    __syncthreads();
    if (tid == 0) {
        int old = atomicAdd(&g_cnt[g], 1);
        misc[3] = (old == 1);
        if (old == 1) g_cnt[g] = 0;        // self-reset for graph replay
    }
    __syncthreads();
    if (misc[3]) {                          // I'm the last of the pair
        __threadfence();                    // acquire
        if (tid < GS) {
            int gi = s_idx[tid];
            if (gi >= 0) {
                float v = *((volatile float*)&g_partial[gi]);
                out[gi] = v;
                *((volatile float*)&g_partial[gi]) = 0.0f;   // self-reset
            }
        }
    }
}

// ---------------------------------------------------------------------------
// Launch: resolve input slots by element count. ONE kernel.
// ---------------------------------------------------------------------------
extern "C" void kernel_launch(void* const* d_in, const int* in_sizes, int n_in,
                              void* d_out, int out_size) {
    const float* head = nullptr;
    const float* tail = nullptr;
    const int*   ids  = nullptr;
    const float* relmat = nullptr;

    for (int i = 0; i < n_in; i++) {
        if (in_sizes[i] == BATCH)                 ids    = (const int*)d_in[i];
        else if (in_sizes[i] == NREL * DIM * DIM) relmat = (const float*)d_in[i];
        else if (in_sizes[i] == BATCH * DIM) {
            if (!head) head = (const float*)d_in[i];
            else       tail = (const float*)d_in[i];
        }
    }
    float* out = (float*)d_out;

    cudaFuncSetAttribute(mma_kernel,
                         cudaFuncAttributeMaxDynamicSharedMemorySize, SMEM_BYTES);

    mma_kernel<<<MAXG * KSPLIT, NTH, SMEM_BYTES>>>(head, tail, relmat, ids, out);
}

// round 13
// speedup vs baseline: 1.3088x; 1.0814x over previous
#include <cuda_runtime.h>
#include <cuda_bf16.h>
#include <cstdint>
#include <cstring>

#define BATCH 4096
#define DIM   256
#define NREL  30
#define GS    32          // samples per group (MMA M dim)
#define MAXG  160         // >= 30 + 4096/32
#define NTH   256
#define KC    32          // K rows per chunk
#define KSPLIT 2          // K halves (CTAs per group)
#define LCHUNKS 4         // chunks per CTA
#define AST   40          // A bf16 tile row stride (halves)
#define BST   264         // B bf16 tile row stride (halves)
#define TST   260         // tT row stride (floats)
#define IDSPT (BATCH / NTH)   // 16 ids per thread

// SMEM byte offsets
#define OFF_SIDX  0                      // 32 ints (128B)
#define OFF_RED   128                    // 512B: epilogue red[128]f; phase0 cnt[32]+wtot[8]
#define OFF_MISC  640                    // 128B flags
#define OFF_ATILE 768                    // [2 mat][32][40] halves = 5120B
#define OFF_BTILE 5888                   // [2 mat][32][264] halves = 33792B
#define OFF_STAGE 39680                  // [2 buf][32][256] fp32 = 65536B
#define SMEM_BYTES 105216                // x2 CTAs = 210432 <= 227KB/SM
// phase0: raw ids staged at OFF_STAGE (<=32KB, inside buf0, dead then)
// epilogue: tT[32][260] fp32 reuses OFF_STAGE

// ---- device scratch (zero-initialized at load; kernel restores zeros) ----
__device__ float g_partial[BATCH];
__device__ int   g_cnt[MAXG];

// ---- helpers ----
__device__ __forceinline__ uint32_t smem_u32(const void* p) {
    uint32_t a;
    asm("{ .reg .u64 t; cvta.to.shared.u64 t, %1; cvt.u32.u64 %0, t; }" : "=r"(a) : "l"(p));
    return a;
}
__device__ __forceinline__ void cpasync16(uint32_t dst, const void* src) {
    asm volatile("cp.async.cg.shared.global [%0], [%1], 16;" :: "r"(dst), "l"(src));
}
__device__ __forceinline__ void ldm_x4(uint32_t* r, uint32_t addr) {
    asm volatile("ldmatrix.sync.aligned.m8n8.x4.shared.b16 {%0,%1,%2,%3}, [%4];"
                 : "=r"(r[0]), "=r"(r[1]), "=r"(r[2]), "=r"(r[3]) : "r"(addr));
}
__device__ __forceinline__ void ldm_x4_t(uint32_t* r, uint32_t addr) {
    asm volatile("ldmatrix.sync.aligned.m8n8.x4.trans.shared.b16 {%0,%1,%2,%3}, [%4];"
                 : "=r"(r[0]), "=r"(r[1]), "=r"(r[2]), "=r"(r[3]) : "r"(addr));
}
__device__ __forceinline__ void mma_bf16(float* c, const uint32_t* a, const uint32_t* b) {
    asm volatile("mma.sync.aligned.m16n8k16.row.col.f32.bf16.bf16.f32 "
                 "{%0,%1,%2,%3}, {%4,%5,%6,%7}, {%8,%9}, {%0,%1,%2,%3};"
                 : "+f"(c[0]), "+f"(c[1]), "+f"(c[2]), "+f"(c[3])
                 : "r"(a[0]), "r"(a[1]), "r"(a[2]), "r"(a[3]), "r"(b[0]), "r"(b[1]));
}
__device__ __forceinline__ void sts8(uint32_t addr, uint32_t lo, uint32_t hi) {
    asm volatile("st.shared.v2.b32 [%0], {%1,%2};" :: "r"(addr), "r"(lo), "r"(hi) : "memory");
}
__device__ __forceinline__ uint32_t bf2bits(__nv_bfloat162 v) {
    uint32_t u; memcpy(&u, &v, 4); return u;
}
__device__ __forceinline__ void split4(float4 v, uint32_t& b0, uint32_t& b1,
                                       uint32_t& s0, uint32_t& s1) {
    __nv_bfloat162 bb0 = __float22bfloat162_rn(make_float2(v.x, v.y));
    __nv_bfloat162 bb1 = __float22bfloat162_rn(make_float2(v.z, v.w));
    float2 f0 = __bfloat1622float2(bb0), f1 = __bfloat1622float2(bb1);
    __nv_bfloat162 ss0 = __float22bfloat162_rn(make_float2(v.x - f0.x, v.y - f0.y));
    __nv_bfloat162 ss1 = __float22bfloat162_rn(make_float2(v.z - f1.x, v.w - f1.y));
    b0 = bf2bits(bb0); b1 = bf2bits(bb1); s0 = bf2bits(ss0); s1 = bf2bits(ss1);
}

// ---------------------------------------------------------------------------
// SINGLE kernel: CTA = (group g, k-half). Phase 0: coalesced SMEM-staged
// grouping (per-CTA redundant, deterministic). Then R10's double-buffered
// 3-pass bf16 mma.sync mainloop. Paired-CTA combine (self-resetting).
// ---------------------------------------------------------------------------
extern __shared__ char smem[];

__global__ __launch_bounds__(NTH, 2)
void mma_kernel(const float* __restrict__ head,
                const float* __restrict__ tail,
                const float* __restrict__ relmat,
                const int* __restrict__ ids32,
                float* __restrict__ out) {
    const int g  = blockIdx.x >> 1;
    const int kh = blockIdx.x & 1;
    const int tid = threadIdx.x, wid = tid >> 5, l = tid & 31;
    uint32_t sb = smem_u32(smem);
    int* s_idx = (int*)(smem + OFF_SIDX);
    float* red = (float*)(smem + OFF_RED);
    int* scr   = (int*)(smem + OFF_RED);
    int* misc  = (int*)(smem + OFF_MISC);

    // ================= Phase 0 (coalesced) ==================================
    // dtype probe: words 1..511 (in-bounds for int32 & int64 buffers)
    int probe = ids32[2 * tid + 1];
    const int stride = __syncthreads_or(probe) ? 1 : 2;   // int32 : int64

    // stage raw id words into SMEM, fully coalesced 16B cp.async
    {
        const int n16 = (BATCH * stride) / 4;             // 1024 or 2048 int4
        const char* src = (const char*)ids32;
        for (int e = tid; e < n16; e += NTH)
            cpasync16(sb + OFF_STAGE + e * 16, src + e * 16);
        asm volatile("cp.async.commit_group;" ::: "memory");
        asm volatile("cp.async.wait_group 0;" ::: "memory");
    }
    if (tid < 32) scr[tid] = 0;
    if (tid < GS) s_idx[tid] = -1;
    __syncthreads();

    // extract my 16 consecutive ids from SMEM + histogram
    const int* sids = (const int*)(smem + OFF_STAGE);
    int my_ids[IDSPT];
    #pragma unroll
    for (int j = 0; j < IDSPT; j++) {
        int v = sids[(tid * IDSPT + j) * stride];
        my_ids[j] = ((unsigned)v < NREL) ? v : 0;
        atomicAdd(&scr[my_ids[j]], 1);
    }
    __syncthreads();

    // g -> (relation, k-slice): all threads redundantly (broadcast LDS)
    int r = -1, kslice = 0;
    {
        int base = 0;
        #pragma unroll
        for (int rr = 0; rr < NREL; rr++) {
            int ngr = (scr[rr] + GS - 1) / GS;
            if (g >= base && g < base + ngr) { r = rr; kslice = g - base; }
            base += ngr;
        }
    }
    if (r < 0) return;                      // dummy group (whole CTA)

    // stable rank scan for relation r (thread-order = index-order)
    {
        int cntm = 0;
        #pragma unroll
        for (int j = 0; j < IDSPT; j++) cntm += (my_ids[j] == r);
        int pre = cntm;
        #pragma unroll
        for (int d = 1; d < 32; d <<= 1) {
            int v = __shfl_up_sync(0xFFFFFFFF, pre, d);
            if (l >= d) pre += v;
        }
        __syncthreads();                    // histogram reads done
        if (l == 31) scr[wid] = pre;        // warp totals (reuse scr[0..7])
        int excl = pre - cntm;
        __syncthreads();
        int base = 0;
        for (int ww = 0; ww < wid; ww++) base += scr[ww];
        int rank = base + excl;
        int lo = kslice * GS, hi = lo + GS;
        #pragma unroll
        for (int j = 0; j < IDSPT; j++) {
            if (my_ids[j] == r) {
                if (rank >= lo && rank < hi) s_idx[rank - lo] = tid * IDSPT + j;
                rank++;
            }
        }
    }
    __syncthreads();

    // ================= Mainloop (R10 verbatim) ==============================
    const int mw = wid & 1;          // m-tile (16 rows)
    const int nw = wid >> 1;         // n-warp (64 cols)
    const float* Mf = relmat + (size_t)r * DIM * DIM + (size_t)kh * (DIM / 2) * DIM;
    const int kbase = kh * (DIM / 2);

    float4 treg[8];
    #pragma unroll
    for (int k = 0; k < 8; k++) {
        int e = tid + k * NTH;
        int s = e >> 6, cc = e & 63;
        int gi = s_idx[s];
        treg[k] = make_float4(0.f, 0.f, 0.f, 0.f);
        if (gi >= 0) treg[k] = ((const float4*)(tail + (size_t)gi * DIM))[cc];
    }

    auto issueB = [&](int kc, int buf) {
        const float* src = Mf + (size_t)kc * KC * DIM;
        #pragma unroll
        for (int k = 0; k < 8; k++) {
            int e = tid + k * NTH;
            cpasync16(sb + OFF_STAGE + buf * 32768 + e * 16, src + e * 4);
        }
        asm volatile("cp.async.commit_group;" ::: "memory");
    };
    issueB(0, 0);
    issueB(1, 1);

    float c[8][4];
    #pragma unroll
    for (int nf = 0; nf < 8; nf++)
        #pragma unroll
        for (int k = 0; k < 4; k++) c[nf][k] = 0.f;

    uint32_t a_row  = mw * 16 + (l & 15);
    uint32_t a_koff = (uint32_t)((l >> 4) << 3);
    uint32_t b_krow = (uint32_t)(l & 15);
    uint32_t b_ncol = (uint32_t)(nw * 64 + ((l >> 4) << 3));

    const int As = tid >> 3, Au = tid & 7;
    const int gia = s_idx[As];

    for (int kc = 0; kc < LCHUNKS; kc++) {
        float4 av = make_float4(0.f, 0.f, 0.f, 0.f);
        if (gia >= 0)
            av = *(const float4*)(head + (size_t)gia * DIM + kbase + kc * KC + Au * 4);

        if (kc == LCHUNKS - 1)
            asm volatile("cp.async.wait_group 0;" ::: "memory");
        else
            asm volatile("cp.async.wait_group 1;" ::: "memory");
        __syncthreads();

        const float4* st4 = (const float4*)(smem + OFF_STAGE + (kc & 1) * 32768);
        #pragma unroll
        for (int k = 0; k < 8; k++) {
            int e = tid + k * NTH;
            int kr = e >> 6, c4 = e & 63;
            uint32_t b0, b1, s0, s1;
            split4(st4[e], b0, b1, s0, s1);
            uint32_t addr = sb + OFF_BTILE + (uint32_t)(kr * (BST * 2) + c4 * 8);
            sts8(addr, b0, b1);
            sts8(addr + 16896, s0, s1);
        }
        {
            uint32_t b0, b1, s0, s1;
            split4(av, b0, b1, s0, s1);
            uint32_t addr = sb + OFF_ATILE + (uint32_t)(As * (AST * 2) + Au * 8);
            sts8(addr, b0, b1);
            sts8(addr + 2560, s0, s1);
        }
        __syncthreads();
        if (kc + 2 < LCHUNKS) issueB(kc + 2, kc & 1);

        uint32_t Ab0 = sb + OFF_ATILE;
        uint32_t Ab1 = sb + OFF_ATILE + 2560;
        uint32_t Bb0 = sb + OFF_BTILE;
        uint32_t Bb1 = sb + OFF_BTILE + 16896;

        #pragma unroll
        for (int ks = 0; ks < KC / 16; ks++) {
            uint32_t aB[4], aS[4];
            uint32_t ka = ks * 16 + a_koff;
            ldm_x4(aB, Ab0 + (a_row * AST + ka) * 2);
            ldm_x4(aS, Ab1 + (a_row * AST + ka) * 2);
            #pragma unroll
            for (int nt = 0; nt < 4; nt++) {
                uint32_t bB[4], bS[4];
                uint32_t boff = ((ks * 16 + b_krow) * BST + b_ncol + nt * 16) * 2;
                ldm_x4_t(bB, Bb0 + boff);
                ldm_x4_t(bS, Bb1 + boff);
                mma_bf16(c[2 * nt],     aB, bB);
                mma_bf16(c[2 * nt + 1], aB, bB + 2);
                mma_bf16(c[2 * nt],     aB, bS);
                mma_bf16(c[2 * nt + 1], aB, bS + 2);
                mma_bf16(c[2 * nt],     aS, bB);
                mma_bf16(c[2 * nt + 1], aS, bB + 2);
            }
        }
    }

    // ================= Epilogue =============================================
    float* tT = (float*)(smem + OFF_STAGE);
    #pragma unroll
    for (int k = 0; k < 8; k++) {
        int e = tid + k * NTH;
        int s = e >> 6, cc = e & 63;
        *(float4*)(tT + s * TST + cc * 4) = treg[k];
    }
    __syncthreads();

    int q = l & 3, a = l >> 2;
    int row0 = mw * 16 + a, row1 = row0 + 8;
    float p0 = 0.f, p1 = 0.f;
    #pragma unroll
    for (int nf = 0; nf < 8; nf++) {
        int j = nw * 64 + nf * 8 + q * 2;
        p0 += c[nf][0] * tT[row0 * TST + j] + c[nf][1] * tT[row0 * TST + j + 1];
        p1 += c[nf][2] * tT[row1 * TST + j] + c[nf][3] * tT[row1 * TST + j + 1];
    }
    p0 += __shfl_xor_sync(0xFFFFFFFF, p0, 1);
    p0 += __shfl_xor_sync(0xFFFFFFFF, p0, 2);
    p1 += __shfl_xor_sync(0xFFFFFFFF, p1, 1);
    p1 += __shfl_xor_sync(0xFFFFFFFF, p1, 2);
    if (q == 0) {
        red[nw * 32 + row0] = p0;
        red[nw * 32 + row1] = p1;
    }
    __syncthreads();

    // release: add partial, fence, then count arrival
    if (tid < GS) {
        int gi = s_idx[tid];
        if (gi >= 0)
            atomicAdd(&g_partial[gi],
                      red[tid] + red[32 + tid] + red[64 + tid] + red[96 + tid]);
        __threadfence();
    }
    __syncthreads();
    if (tid == 0) {
        int old = atomicAdd(&g_cnt[g], 1);
        misc[3] = (old == 1);
        if (old == 1) g_cnt[g] = 0;        // self-reset for graph replay
    }
    __syncthreads();
    if (misc[3]) {                          // last CTA of the pair
        __threadfence();                    // acquire
        if (tid < GS) {
            int gi = s_idx[tid];
            if (gi >= 0) {
                float v = *((volatile float*)&g_partial[gi]);
                out[gi] = v;
                *((volatile float*)&g_partial[gi]) = 0.0f;   // self-reset
            }
        }
    }
}

// ---------------------------------------------------------------------------
// Launch: resolve input slots by element count. ONE kernel.
// ---------------------------------------------------------------------------
extern "C" void kernel_launch(void* const* d_in, const int* in_sizes, int n_in,
                              void* d_out, int out_size) {
    const float* head = nullptr;
    const float* tail = nullptr;
    const int*   ids  = nullptr;
    const float* relmat = nullptr;

    for (int i = 0; i < n_in; i++) {
        if (in_sizes[i] == BATCH)                 ids    = (const int*)d_in[i];
        else if (in_sizes[i] == NREL * DIM * DIM) relmat = (const float*)d_in[i];
        else if (in_sizes[i] == BATCH * DIM) {
            if (!head) head = (const float*)d_in[i];
            else       tail = (const float*)d_in[i];
        }
    }
    float* out = (float*)d_out;

    cudaFuncSetAttribute(mma_kernel,
                         cudaFuncAttributeMaxDynamicSharedMemorySize, SMEM_BYTES);

    mma_kernel<<<MAXG * KSPLIT, NTH, SMEM_BYTES>>>(head, tail, relmat, ids, out);
}

// round 14
// speedup vs baseline: 1.4153x; 1.0814x over previous
#include <cuda_runtime.h>
#include <cuda_bf16.h>
#include <cstdint>
#include <cstring>

#define BATCH 4096
#define DIM   256
#define NREL  30
#define GS    32          // samples per group (MMA M dim)
#define MAXG  160         // >= 30 + 4096/32
#define NTH   256
#define KC    32          // K rows per chunk
#define KSPLIT 2          // K halves (CTAs per group)
#define LCHUNKS 4         // chunks per CTA
#define AST   40          // A bf16 tile row stride (halves)
#define BST   264         // B bf16 tile row stride (halves)
#define TST   260         // tT row stride (floats)
#define IDSPT (BATCH / NTH)   // 16 ids per thread

// SMEM byte offsets
#define OFF_SIDX  0                      // 32 ints (128B)
#define OFF_RED   128                    // 512B: epilogue red[128]f; phase0 cnt[32]+wtot[8]
#define OFF_MISC  640                    // 128B flags
#define OFF_ATILE 768                    // [2 mat][32][40] halves = 5120B
#define OFF_BTILE 5888                   // [2 mat][32][264] halves = 33792B
#define OFF_STAGE 39680                  // [2 buf][32][256] fp32 = 65536B
#define SMEM_BYTES 105216                // x2 CTAs = 210432 <= 227KB/SM
// epilogue: tT[32][260] fp32 reuses OFF_STAGE

// ---- device scratch (zero-initialized at load; kernel restores zeros) ----
__device__ float g_partial[BATCH];
__device__ int   g_cnt[MAXG];

// ---- helpers ----
__device__ __forceinline__ uint32_t smem_u32(const void* p) {
    uint32_t a;
    asm("{ .reg .u64 t; cvta.to.shared.u64 t, %1; cvt.u32.u64 %0, t; }" : "=r"(a) : "l"(p));
    return a;
}
__device__ __forceinline__ void cpasync16(uint32_t dst, const void* src) {
    asm volatile("cp.async.cg.shared.global [%0], [%1], 16;" :: "r"(dst), "l"(src));
}
__device__ __forceinline__ void ldm_x4(uint32_t* r, uint32_t addr) {
    asm volatile("ldmatrix.sync.aligned.m8n8.x4.shared.b16 {%0,%1,%2,%3}, [%4];"
                 : "=r"(r[0]), "=r"(r[1]), "=r"(r[2]), "=r"(r[3]) : "r"(addr));
}
__device__ __forceinline__ void ldm_x4_t(uint32_t* r, uint32_t addr) {
    asm volatile("ldmatrix.sync.aligned.m8n8.x4.trans.shared.b16 {%0,%1,%2,%3}, [%4];"
                 : "=r"(r[0]), "=r"(r[1]), "=r"(r[2]), "=r"(r[3]) : "r"(addr));
}
__device__ __forceinline__ void mma_bf16(float* c, const uint32_t* a, const uint32_t* b) {
    asm volatile("mma.sync.aligned.m16n8k16.row.col.f32.bf16.bf16.f32 "
                 "{%0,%1,%2,%3}, {%4,%5,%6,%7}, {%8,%9}, {%0,%1,%2,%3};"
                 : "+f"(c[0]), "+f"(c[1]), "+f"(c[2]), "+f"(c[3])
                 : "r"(a[0]), "r"(a[1]), "r"(a[2]), "r"(a[3]), "r"(b[0]), "r"(b[1]));
}
__device__ __forceinline__ void sts8(uint32_t addr, uint32_t lo, uint32_t hi) {
    asm volatile("st.shared.v2.b32 [%0], {%1,%2};" :: "r"(addr), "r"(lo), "r"(hi) : "memory");
}
__device__ __forceinline__ uint32_t bf2bits(__nv_bfloat162 v) {
    uint32_t u; memcpy(&u, &v, 4); return u;
}
__device__ __forceinline__ void split4(float4 v, uint32_t& b0, uint32_t& b1,
                                       uint32_t& s0, uint32_t& s1) {
    __nv_bfloat162 bb0 = __float22bfloat162_rn(make_float2(v.x, v.y));
    __nv_bfloat162 bb1 = __float22bfloat162_rn(make_float2(v.z, v.w));
    float2 f0 = __bfloat1622float2(bb0), f1 = __bfloat1622float2(bb1);
    __nv_bfloat162 ss0 = __float22bfloat162_rn(make_float2(v.x - f0.x, v.y - f0.y));
    __nv_bfloat162 ss1 = __float22bfloat162_rn(make_float2(v.z - f1.x, v.w - f1.y));
    b0 = bf2bits(bb0); b1 = bf2bits(bb1); s0 = bf2bits(ss0); s1 = bf2bits(ss1);
}

// ---------------------------------------------------------------------------
// SINGLE kernel: CTA = (group g, k-half). Phase 0: direct coalesced id reads
// with transposed ownership (thread t owns samples {j*256+t}); deterministic
// (same function of data in every CTA). Then R10's double-buffered 3-pass
// bf16 mma.sync mainloop. Paired-CTA combine (self-resetting).
// ---------------------------------------------------------------------------
extern __shared__ char smem[];

__global__ __launch_bounds__(NTH, 2)
void mma_kernel(const float* __restrict__ head,
                const float* __restrict__ tail,
                const float* __restrict__ relmat,
                const int* __restrict__ ids32,
                float* __restrict__ out) {
    const int g  = blockIdx.x >> 1;
    const int kh = blockIdx.x & 1;
    const int tid = threadIdx.x, wid = tid >> 5, l = tid & 31;
    uint32_t sb = smem_u32(smem);
    int* s_idx = (int*)(smem + OFF_SIDX);
    float* red = (float*)(smem + OFF_RED);
    int* scr   = (int*)(smem + OFF_RED);
    int* misc  = (int*)(smem + OFF_MISC);

    // ================= Phase 0 ==============================================
    // dtype probe: words 1..511 (in-bounds for int32 & int64 buffers)
    int probe = ids32[2 * tid + 1];
    if (tid < 32) scr[tid] = 0;
    if (tid < GS) s_idx[tid] = -1;
    const int stride = __syncthreads_or(probe) ? 1 : 2;   // int32 : int64

    // coalesced direct reads: thread t owns samples {j*NTH + t}
    int my_ids[IDSPT];
    #pragma unroll
    for (int j = 0; j < IDSPT; j++) {
        int v = ids32[(j * NTH + tid) * stride];
        my_ids[j] = ((unsigned)v < NREL) ? v : 0;
    }
    #pragma unroll
    for (int j = 0; j < IDSPT; j++)
        atomicAdd(&scr[my_ids[j]], 1);
    __syncthreads();

    // g -> (relation, k-slice): all threads redundantly (broadcast LDS)
    int r = -1, kslice = 0;
    {
        int base = 0;
        #pragma unroll
        for (int rr = 0; rr < NREL; rr++) {
            int ngr = (scr[rr] + GS - 1) / GS;
            if (g >= base && g < base + ngr) { r = rr; kslice = g - base; }
            base += ngr;
        }
    }
    if (r < 0) return;                      // dummy group (whole CTA)

    // stable rank scan for relation r, order key = (tid, j). Deterministic:
    // identical function of the id data in every CTA and every replay.
    {
        int cntm = 0;
        #pragma unroll
        for (int j = 0; j < IDSPT; j++) cntm += (my_ids[j] == r);
        int pre = cntm;
        #pragma unroll
        for (int d = 1; d < 32; d <<= 1) {
            int v = __shfl_up_sync(0xFFFFFFFF, pre, d);
            if (l >= d) pre += v;
        }
        __syncthreads();                    // histogram reads done
        if (l == 31) scr[wid] = pre;        // warp totals (reuse scr[0..7])
        int excl = pre - cntm;
        __syncthreads();
        int base = 0;
        for (int ww = 0; ww < wid; ww++) base += scr[ww];
        int rank = base + excl;
        int lo = kslice * GS, hi = lo + GS;
        #pragma unroll
        for (int j = 0; j < IDSPT; j++) {
            if (my_ids[j] == r) {
                if (rank >= lo && rank < hi) s_idx[rank - lo] = j * NTH + tid;
                rank++;
            }
        }
    }
    __syncthreads();

    // ================= Mainloop (R10 verbatim) ==============================
    const int mw = wid & 1;          // m-tile (16 rows)
    const int nw = wid >> 1;         // n-warp (64 cols)
    const float* Mf = relmat + (size_t)r * DIM * DIM + (size_t)kh * (DIM / 2) * DIM;
    const int kbase = kh * (DIM / 2);

    float4 treg[8];
    #pragma unroll
    for (int k = 0; k < 8; k++) {
        int e = tid + k * NTH;
        int s = e >> 6, cc = e & 63;
        int gi = s_idx[s];
        treg[k] = make_float4(0.f, 0.f, 0.f, 0.f);
        if (gi >= 0) treg[k] = ((const float4*)(tail + (size_t)gi * DIM))[cc];
    }

    auto issueB = [&](int kc, int buf) {
        const float* src = Mf + (size_t)kc * KC * DIM;
        #pragma unroll
        for (int k = 0; k < 8; k++) {
            int e = tid + k * NTH;
            cpasync16(sb + OFF_STAGE + buf * 32768 + e * 16, src + e * 4);
        }
        asm volatile("cp.async.commit_group;" ::: "memory");
    };
    issueB(0, 0);
    issueB(1, 1);

    float c[8][4];
    #pragma unroll
    for (int nf = 0; nf < 8; nf++)
        #pragma unroll
        for (int k = 0; k < 4; k++) c[nf][k] = 0.f;

    uint32_t a_row  = mw * 16 + (l & 15);
    uint32_t a_koff = (uint32_t)((l >> 4) << 3);
    uint32_t b_krow = (uint32_t)(l & 15);
    uint32_t b_ncol = (uint32_t)(nw * 64 + ((l >> 4) << 3));

    const int As = tid >> 3, Au = tid & 7;
    const int gia = s_idx[As];

    for (int kc = 0; kc < LCHUNKS; kc++) {
        float4 av = make_float4(0.f, 0.f, 0.f, 0.f);
        if (gia >= 0)
            av = *(const float4*)(head + (size_t)gia * DIM + kbase + kc * KC + Au * 4);

        if (kc == LCHUNKS - 1)
            asm volatile("cp.async.wait_group 0;" ::: "memory");
        else
            asm volatile("cp.async.wait_group 1;" ::: "memory");
        __syncthreads();

        const float4* st4 = (const float4*)(smem + OFF_STAGE + (kc & 1) * 32768);
        #pragma unroll
        for (int k = 0; k < 8; k++) {
            int e = tid + k * NTH;
            int kr = e >> 6, c4 = e & 63;
            uint32_t b0, b1, s0, s1;
            split4(st4[e], b0, b1, s0, s1);
            uint32_t addr = sb + OFF_BTILE + (uint32_t)(kr * (BST * 2) + c4 * 8);
            sts8(addr, b0, b1);
            sts8(addr + 16896, s0, s1);
        }
        {
            uint32_t b0, b1, s0, s1;
            split4(av, b0, b1, s0, s1);
            uint32_t addr = sb + OFF_ATILE + (uint32_t)(As * (AST * 2) + Au * 8);
            sts8(addr, b0, b1);
            sts8(addr + 2560, s0, s1);
        }
        __syncthreads();
        if (kc + 2 < LCHUNKS) issueB(kc + 2, kc & 1);

        uint32_t Ab0 = sb + OFF_ATILE;
        uint32_t Ab1 = sb + OFF_ATILE + 2560;
        uint32_t Bb0 = sb + OFF_BTILE;
        uint32_t Bb1 = sb + OFF_BTILE + 16896;

        #pragma unroll
        for (int ks = 0; ks < KC / 16; ks++) {
            uint32_t aB[4], aS[4];
            uint32_t ka = ks * 16 + a_koff;
            ldm_x4(aB, Ab0 + (a_row * AST + ka) * 2);
            ldm_x4(aS, Ab1 + (a_row * AST + ka) * 2);
            #pragma unroll
            for (int nt = 0; nt < 4; nt++) {
                uint32_t bB[4], bS[4];
                uint32_t boff = ((ks * 16 + b_krow) * BST + b_ncol + nt * 16) * 2;
                ldm_x4_t(bB, Bb0 + boff);
                ldm_x4_t(bS, Bb1 + boff);
                mma_bf16(c[2 * nt],     aB, bB);
                mma_bf16(c[2 * nt + 1], aB, bB + 2);
                mma_bf16(c[2 * nt],     aB, bS);
                mma_bf16(c[2 * nt + 1], aB, bS + 2);
                mma_bf16(c[2 * nt],     aS, bB);
                mma_bf16(c[2 * nt + 1], aS, bB + 2);
            }
        }
    }

    // ================= Epilogue =============================================
    float* tT = (float*)(smem + OFF_STAGE);
    #pragma unroll
    for (int k = 0; k < 8; k++) {
        int e = tid + k * NTH;
        int s = e >> 6, cc = e & 63;
        *(float4*)(tT + s * TST + cc * 4) = treg[k];
    }
    __syncthreads();

    int q = l & 3, a = l >> 2;
    int row0 = mw * 16 + a, row1 = row0 + 8;
    float p0 = 0.f, p1 = 0.f;
    #pragma unroll
    for (int nf = 0; nf < 8; nf++) {
        int j = nw * 64 + nf * 8 + q * 2;
        p0 += c[nf][0] * tT[row0 * TST + j] + c[nf][1] * tT[row0 * TST + j + 1];
        p1 += c[nf][2] * tT[row1 * TST + j] + c[nf][3] * tT[row1 * TST + j + 1];
    }
    p0 += __shfl_xor_sync(0xFFFFFFFF, p0, 1);
    p0 += __shfl_xor_sync(0xFFFFFFFF, p0, 2);
    p1 += __shfl_xor_sync(0xFFFFFFFF, p1, 1);
    p1 += __shfl_xor_sync(0xFFFFFFFF, p1, 2);
    if (q == 0) {
        red[nw * 32 + row0] = p0;
        red[nw * 32 + row1] = p1;
    }
    __syncthreads();

    // release: add partial, fence, then count arrival
    if (tid < GS) {
        int gi = s_idx[tid];
        if (gi >= 0)
            atomicAdd(&g_partial[gi],
                      red[tid] + red[32 + tid] + red[64 + tid] + red[96 + tid]);
        __threadfence();
    }
    __syncthreads();
    if (tid == 0) {
        int old = atomicAdd(&g_cnt[g], 1);
        misc[3] = (old == 1);
        if (old == 1) g_cnt[g] = 0;        // self-reset for graph replay
    }
    __syncthreads();
    if (misc[3]) {                          // last CTA of the pair
        __threadfence();                    // acquire
        if (tid < GS) {
            int gi = s_idx[tid];
            if (gi >= 0) {
                float v = *((volatile float*)&g_partial[gi]);
                out[gi] = v;
                *((volatile float*)&g_partial[gi]) = 0.0f;   // self-reset
            }
        }
    }
}

// ---------------------------------------------------------------------------
// Launch: resolve input slots by element count. ONE kernel.
// ---------------------------------------------------------------------------
extern "C" void kernel_launch(void* const* d_in, const int* in_sizes, int n_in,
                              void* d_out, int out_size) {
    const float* head = nullptr;
    const float* tail = nullptr;
    const int*   ids  = nullptr;
    const float* relmat = nullptr;

    for (int i = 0; i < n_in; i++) {
        if (in_sizes[i] == BATCH)                 ids    = (const int*)d_in[i];
        else if (in_sizes[i] == NREL * DIM * DIM) relmat = (const float*)d_in[i];
        else if (in_sizes[i] == BATCH * DIM) {
            if (!head) head = (const float*)d_in[i];
            else       tail = (const float*)d_in[i];
        }
    }
    float* out = (float*)d_out;

    cudaFuncSetAttribute(mma_kernel,
                         cudaFuncAttributeMaxDynamicSharedMemorySize, SMEM_BYTES);

    mma_kernel<<<MAXG * KSPLIT, NTH, SMEM_BYTES>>>(head, tail, relmat, ids, out);
}